// round 16
// baseline (speedup 1.0000x reference)
#include <cuda_runtime.h>
#include <cuda_fp16.h>
#include <cstdint>

#define T_ 4
#define B_ 32
#define C_ 512
#define N_ 256
#define H_ 8
#define D_ 64
#define BCN_ (B_*C_*N_)
#define TBCN_ (T_*BCN_)

// ---- scratch ----
__device__ __half g_kh[TBCN_];         // [tb][c][n] fp16 spikes
__device__ __half g_vh[TBCN_];
__device__ __half g_qT[TBCN_];         // [tb][n][c] fp16 spikes
__device__ __half g_xsT[TBCN_];        // [t][b][n][c] spikes fp16 (K-major)
__device__ __half g_sT[TBCN_];         // [tb][n][c] attn spikes fp16
__device__ __half g_wl[4*2*C_*C_];     // [mat][limb][o][c] fp16 weight limbs

// ================= helpers =================
__device__ __forceinline__ uint32_t smem_u32(const void* p) {
    uint32_t a;
    asm("{ .reg .u64 t; cvta.to.shared.u64 t, %1; cvt.u32.u64 %0, t; }" : "=r"(a) : "l"(p));
    return a;
}

#define CP16(dst, src) \
    asm volatile("cp.async.cg.shared.global [%0], [%1], 16;" :: "r"(dst), "l"(src))
#define CP_COMMIT() asm volatile("cp.async.commit_group;" ::: "memory")
#define CP_WAIT(n)  asm volatile("cp.async.wait_group %0;" :: "n"(n) : "memory")

__device__ __forceinline__ void ldm_x4(uint32_t r[4], uint32_t addr) {
    asm volatile("ldmatrix.sync.aligned.m8n8.x4.shared.b16 {%0,%1,%2,%3}, [%4];"
        : "=r"(r[0]), "=r"(r[1]), "=r"(r[2]), "=r"(r[3]) : "r"(addr));
}
__device__ __forceinline__ void mma16816(float c[4], const uint32_t a[4], const uint32_t* b) {
    asm volatile("mma.sync.aligned.m16n8k16.row.col.f32.f16.f16.f32 "
        "{%0,%1,%2,%3}, {%4,%5,%6,%7}, {%8,%9}, {%0,%1,%2,%3};"
        : "+f"(c[0]), "+f"(c[1]), "+f"(c[2]), "+f"(c[3])
        : "r"(a[0]), "r"(a[1]), "r"(a[2]), "r"(a[3]), "r"(b[0]), "r"(b[1]));
}

__device__ __forceinline__ float lif_step(float& v, float x, float vth) {
    v += (x - v) * 0.5f;
    float s = (v >= vth) ? 1.0f : 0.0f;
    if (s != 0.0f) v = 0.0f;
    return s;
}
__device__ __forceinline__ uint32_t hpair(float lo, float hi) {
    return (uint32_t)__half_as_ushort(__float2half_rn(lo)) |
           ((uint32_t)__half_as_ushort(__float2half_rn(hi)) << 16);
}
__device__ __forceinline__ uint32_t hpack(__half lo, __half hi) {
    return (uint32_t)__half_as_ushort(lo) | ((uint32_t)__half_as_ushort(hi) << 16);
}

// ============================================================
// K0+K1 merged prep: blocks [0,1024) = weight limb split (x4 vec),
// blocks [1024,2048) = LIF(x) -> fp16 spikes [t][b][n][c].
// ============================================================
__global__ __launch_bounds__(256) void prep_kernel(
    const float* __restrict__ x,
    const float* __restrict__ qw, const float* __restrict__ kw,
    const float* __restrict__ vw, const float* __restrict__ pw)
{
    __shared__ __half Sb[64][72];
    if (blockIdx.x < 1024) {
        int i = blockIdx.x * 256 + threadIdx.x;      // 0..262143: float4 groups
        int mat = i >> 16, g = i & 65535;
        int idx = g * 4;
        const float* W = (mat == 0) ? qw : (mat == 1) ? kw : (mat == 2) ? vw : pw;
        float4 w4 = *(const float4*)(W + idx);
        float w[4] = {w4.x, w4.y, w4.z, w4.w};
        __half h1[4], h2[4];
        #pragma unroll
        for (int p = 0; p < 4; p++) {
            h1[p] = __float2half_rn(w[p]);
            float r1 = w[p] - __half2float(h1[p]);
            h2[p] = __float2half_rn(r1);
        }
        size_t base = (size_t)(mat * 2) * 262144 + idx;
        *(uint2*)(g_wl + base)          = make_uint2(hpack(h1[0], h1[1]), hpack(h1[2], h1[3]));
        *(uint2*)(g_wl + base + 262144) = make_uint2(hpack(h2[0], h2[1]), hpack(h2[2], h2[3]));
        return;
    }
    int bx = blockIdx.x - 1024;
    int ch = bx & 7, nt = (bx >> 3) & 3, b = bx >> 5;
    int tid = threadIdx.x;
    int c_l = tid >> 2, ng = tid & 3;
    int n_o = tid >> 2, u0 = tid & 3;
    float vm[16];
    #pragma unroll
    for (int j = 0; j < 16; j++) vm[j] = 0.f;

    for (int t = 0; t < T_; t++) {
        const float* xp = x + (((size_t)(t * B_ + b)) * C_ + ch * 64 + c_l) * N_ + nt * 64 + ng * 16;
        #pragma unroll
        for (int q = 0; q < 4; q++) {
            float4 xv = *(const float4*)(xp + q * 4);
            Sb[c_l][ng*16 + q*4 + 0] = __float2half_rn(lif_step(vm[q*4+0], xv.x, 1.0f));
            Sb[c_l][ng*16 + q*4 + 1] = __float2half_rn(lif_step(vm[q*4+1], xv.y, 1.0f));
            Sb[c_l][ng*16 + q*4 + 2] = __float2half_rn(lif_step(vm[q*4+2], xv.z, 1.0f));
            Sb[c_l][ng*16 + q*4 + 3] = __float2half_rn(lif_step(vm[q*4+3], xv.w, 1.0f));
        }
        __syncthreads();
        char* outb = (char*)(g_xsT + ((size_t)(t*B_ + b) * N_ + nt*64 + n_o) * C_ + ch*64);
        #pragma unroll
        for (int hf = 0; hf < 2; hf++) {
            int u = u0 + hf * 4;
            uint32_t rp[4];
            #pragma unroll
            for (int p = 0; p < 4; p++) {
                float lo = __half2float(Sb[u*8 + p*2][n_o]);
                float hi = __half2float(Sb[u*8 + p*2 + 1][n_o]);
                rp[p] = hpair(lo, hi);
            }
            *(uint4*)(outb + u*16) = make_uint4(rp[0], rp[1], rp[2], rp[3]);
        }
        __syncthreads();
    }
}

// ============================================================
// M64 GEMM machinery: 64x128 block, 8 warps (2m x 4n), warp 32x32.
// Single-t variant (proj) and t4 variant (qkv: all 4 timesteps).
// ============================================================
#define B_STAGE_BYTES (128*24*2)
#define B4_STAGE_BYTES (512*24*2)
#define A64_STAGE_BYTES (2*64*24*2)
#define NSTG 4
#define GEMM64_SMEM   (NSTG*A64_STAGE_BYTES + NSTG*B_STAGE_BYTES)
#define GEMM64T4_SMEM (NSTG*A64_STAGE_BYTES + NSTG*B4_STAGE_BYTES)

__device__ __forceinline__ void load_stage_B(uint32_t bsb, int s, int kc,
                                             const __half* srcT, int rowbase, int tid) {
    int n = tid >> 1, h = tid & 1;
    const __half* src = srcT + ((size_t)(rowbase + n)) * 512 + kc + h*8;
    uint32_t dst = bsb + (uint32_t)(((s*128 + n)*24 + h*8) * 2);
    CP16(dst, src);
}
__device__ __forceinline__ void load_stage_B4(uint32_t bsb, int s, int kc,
                                              const __half* srcT, const int rb[4], int tid) {
    int n = tid >> 1, h = tid & 1;
    #pragma unroll
    for (int t = 0; t < 4; t++)
        CP16(bsb + (uint32_t)(((s*512 + t*128 + n)*24 + h*8) * 2),
             srcT + ((size_t)(rb[t] + n)) * 512 + kc + h*8);
}
__device__ __forceinline__ void load_stage_A64(uint32_t asb, int s, int kc, int wmat, int mt, int tid) {
    int l = tid >> 7, rem = tid & 127;
    int o = rem >> 1, h = rem & 1;
    const __half* src = g_wl + ((size_t)(wmat*2 + l) * 512 + mt*64 + o) * 512 + kc + h*8;
    uint32_t dst = asb + (uint32_t)((((s*2 + l)*64 + o)*24 + h*8) * 2);
    CP16(dst, src);
}

// single-t pass (proj)
__device__ __forceinline__ void gemm_pass64(uint32_t asb, uint32_t bsb, float acc[2][4][4],
                                            int wmat, int mt, const __half* srcT, int rowbase,
                                            int tid, int wm, int wn, int lane) {
    #pragma unroll
    for (int p = 0; p < 3; p++) {
        load_stage_A64(asb, p, p*16, wmat, mt, tid);
        load_stage_B(bsb, p, p*16, srcT, rowbase, tid);
        CP_COMMIT();
    }
    int a_row = lane & 15, a_col = (lane >> 4) * 8;
    int b_row = wn + (lane & 7) + ((lane >> 4) << 3), b_col = lane & 8;

    int s = 0;
    for (int c = 0; c < 32; c++) {
        CP_WAIT(2);
        __syncthreads();
        if (c + 3 < 32) {
            int ns = s + 3; if (ns >= NSTG) ns -= NSTG;
            load_stage_A64(asb, ns, (c+3)*16, wmat, mt, tid);
            load_stage_B(bsb, ns, (c+3)*16, srcT, rowbase, tid);
        }
        CP_COMMIT();

        uint32_t bfr[4][2];
        #pragma unroll
        for (int jp = 0; jp < 2; jp++) {
            uint32_t r4[4];
            ldm_x4(r4, bsb + (uint32_t)((((s*128) + b_row + jp*16)*24 + b_col) * 2));
            bfr[jp*2][0] = r4[0];   bfr[jp*2][1] = r4[1];
            bfr[jp*2+1][0] = r4[2]; bfr[jp*2+1][1] = r4[3];
        }
        #pragma unroll
        for (int l = 0; l < 2; l++) {
            #pragma unroll
            for (int i = 0; i < 2; i++) {
                uint32_t a4[4];
                ldm_x4(a4, asb + (uint32_t)(((((s*2 + l)*64) + wm + i*16 + a_row)*24 + a_col) * 2));
                #pragma unroll
                for (int j = 0; j < 4; j++)
                    mma16816(acc[i][j], a4, bfr[j]);
            }
        }
        if (++s >= NSTG) s = 0;
    }
}

// t4 pass (qkv): acc[t][i][j][4], A frags reused for all 4 t.
__device__ __forceinline__ void gemm_pass64_t4(uint32_t asb, uint32_t bsb, float acc[4][2][4][4],
                                               int wmat, int mt, const __half* srcT,
                                               const int rb[4],
                                               int tid, int wm, int wn, int lane) {
    #pragma unroll
    for (int p = 0; p < 3; p++) {
        load_stage_A64(asb, p, p*16, wmat, mt, tid);
        load_stage_B4(bsb, p, p*16, srcT, rb, tid);
        CP_COMMIT();
    }
    int a_row = lane & 15, a_col = (lane >> 4) * 8;
    int b_row = wn + (lane & 7) + ((lane >> 4) << 3), b_col = lane & 8;

    int s = 0;
    for (int c = 0; c < 32; c++) {
        CP_WAIT(2);
        __syncthreads();
        if (c + 3 < 32) {
            int ns = s + 3; if (ns >= NSTG) ns -= NSTG;
            load_stage_A64(asb, ns, (c+3)*16, wmat, mt, tid);
            load_stage_B4(bsb, ns, (c+3)*16, srcT, rb, tid);
        }
        CP_COMMIT();

        uint32_t bfr[4][4][2];
        #pragma unroll
        for (int t = 0; t < 4; t++) {
            #pragma unroll
            for (int jp = 0; jp < 2; jp++) {
                uint32_t r4[4];
                ldm_x4(r4, bsb + (uint32_t)((((s*512 + t*128) + b_row + jp*16)*24 + b_col) * 2));
                bfr[t][jp*2][0] = r4[0];   bfr[t][jp*2][1] = r4[1];
                bfr[t][jp*2+1][0] = r4[2]; bfr[t][jp*2+1][1] = r4[3];
            }
        }
        #pragma unroll
        for (int l = 0; l < 2; l++) {
            #pragma unroll
            for (int i = 0; i < 2; i++) {
                uint32_t a4[4];
                ldm_x4(a4, asb + (uint32_t)(((((s*2 + l)*64) + wm + i*16 + a_row)*24 + a_col) * 2));
                #pragma unroll
                for (int t = 0; t < 4; t++)
                    #pragma unroll
                    for (int j = 0; j < 4; j++)
                        mma16816(acc[t][i][j], a4, bfr[t][j]);
            }
        }
        if (++s >= NSTG) s = 0;
    }
}

// ============================================================
// K2: qkv GEMM (M64, t4) + BN + LIF.  q writes g_qT [n][c],
// k/v write [c][n]; all branches stage tiles in smem for coalesced
// uint4 stores.  grid.x=512, grid.y=3.
// ============================================================
__global__ __launch_bounds__(256, 1) void qkv_mma_kernel(
    const float* __restrict__ qg, const float* __restrict__ qb, const float* __restrict__ qm, const float* __restrict__ qv,
    const float* __restrict__ kg, const float* __restrict__ kb, const float* __restrict__ km, const float* __restrict__ kvv,
    const float* __restrict__ vg, const float* __restrict__ vb, const float* __restrict__ vmn, const float* __restrict__ vvv)
{
    extern __shared__ char dynsmem[];
    uint32_t asb = smem_u32(dynsmem), bsb = asb + NSTG*A64_STAGE_BYTES;
    int tid = threadIdx.x, lane = tid & 31, wid = tid >> 5;
    int wm = (wid & 1) * 32, wn = (wid >> 1) * 32;
    int bx = blockIdx.x, br = blockIdx.y;
    int nt = bx & 1, mt = (bx >> 1) & 7, b = bx >> 4;

    const float* G  = (br == 0) ? qg : (br == 1) ? kg : vg;
    const float* Bt = (br == 0) ? qb : (br == 1) ? kb : vb;
    const float* M  = (br == 0) ? qm : (br == 1) ? km : vmn;
    const float* V  = (br == 0) ? qv : (br == 1) ? kvv : vvv;
    __half* outp = (br == 1) ? g_kh : g_vh;

    float scl[2][2], mean[2][2], beta[2][2];
    #pragma unroll
    for (int i = 0; i < 2; i++)
        #pragma unroll
        for (int rh = 0; rh < 2; rh++) {
            int o = mt*64 + wm + i*16 + rh*8 + (lane >> 2);
            scl[i][rh]  = G[o] / sqrtf(V[o] + 1e-5f);
            mean[i][rh] = M[o];
            beta[i][rh] = Bt[o];
        }

    float vm[2][2][4][2];
    #pragma unroll
    for (int i = 0; i < 2; i++)
        #pragma unroll
        for (int rh = 0; rh < 2; rh++)
            #pragma unroll
            for (int j = 0; j < 4; j++) { vm[i][rh][j][0] = 0.f; vm[i][rh][j][1] = 0.f; }

    float acc[4][2][4][4];
    #pragma unroll
    for (int t = 0; t < 4; t++)
        #pragma unroll
        for (int i = 0; i < 2; i++)
            #pragma unroll
            for (int j = 0; j < 4; j++)
                #pragma unroll
                for (int p = 0; p < 4; p++) acc[t][i][j][p] = 0.f;

    int rb[4];
    #pragma unroll
    for (int t = 0; t < 4; t++) rb[t] = (t*B_ + b) * 256 + nt*128;

    gemm_pass64_t4(asb, bsb, acc, br, mt, g_xsT, rb, tid, wm, wn, lane);

    #pragma unroll
    for (int t = 0; t < 4; t++) {
        if (br == 0) {
            __syncthreads();
            __half* Sq = (__half*)dynsmem;   // [n 128][o 64] stride 72
            #pragma unroll
            for (int i = 0; i < 2; i++) {
                #pragma unroll
                for (int j = 0; j < 4; j++) {
                    #pragma unroll
                    for (int rh = 0; rh < 2; rh++) {
                        float y0 = (acc[t][i][j][rh*2+0] - mean[i][rh]) * scl[i][rh] + beta[i][rh];
                        float y1 = (acc[t][i][j][rh*2+1] - mean[i][rh]) * scl[i][rh] + beta[i][rh];
                        float s0 = lif_step(vm[i][rh][j][0], y0, 1.0f);
                        float s1 = lif_step(vm[i][rh][j][1], y1, 1.0f);
                        int o_l = wm + i*16 + rh*8 + (lane >> 2);
                        int n_l = wn + j*8 + 2*(lane & 3);
                        Sq[n_l*72 + o_l]     = __float2half_rn(s0);
                        Sq[(n_l+1)*72 + o_l] = __float2half_rn(s1);
                    }
                }
            }
            __syncthreads();
            #pragma unroll
            for (int r = 0; r < 2; r++) {
                int idx = tid + r * 256;
                int row = idx >> 3, chk = idx & 7;
                *(uint4*)(g_qT + ((size_t)(t*B_ + b) * N_ + nt*128 + row) * C_ + mt*64 + chk*8) =
                    *(const uint4*)(&Sq[row*72 + chk*8]);
            }
            __syncthreads();
        } else {
            __syncthreads();
            __half* Sk = (__half*)dynsmem;   // [o 64][n 128] stride 136
            #pragma unroll
            for (int i = 0; i < 2; i++) {
                #pragma unroll
                for (int j = 0; j < 4; j++) {
                    #pragma unroll
                    for (int rh = 0; rh < 2; rh++) {
                        float y0 = (acc[t][i][j][rh*2+0] - mean[i][rh]) * scl[i][rh] + beta[i][rh];
                        float y1 = (acc[t][i][j][rh*2+1] - mean[i][rh]) * scl[i][rh] + beta[i][rh];
                        float s0 = lif_step(vm[i][rh][j][0], y0, 1.0f);
                        float s1 = lif_step(vm[i][rh][j][1], y1, 1.0f);
                        int o_l = wm + i*16 + rh*8 + (lane >> 2);
                        int n_l = wn + j*8 + 2*(lane & 3);
                        *(uint32_t*)(&Sk[o_l*136 + n_l]) = hpair(s0, s1);
                    }
                }
            }
            __syncthreads();
            #pragma unroll
            for (int r = 0; r < 4; r++) {
                int idx = tid + r * 256;           // 1024 uint4: 64 rows x 16 chunks
                int row = idx >> 4, chk = idx & 15;
                *(uint4*)(outp + ((size_t)(t*B_ + b) * C_ + mt*64 + row) * N_ + nt*128 + chk*8) =
                    *(const uint4*)(&Sk[row*136 + chk*8]);
            }
            __syncthreads();
        }
    }
}

// ============================================================
// K3 fused (verified round-13 version): per (b,h) block: for each
// t, kv = 0.125*v@k^T via MMA (kept in smem), then a = q@kv^T via
// MMA, LIF(0.5), spikes -> g_sT.
// ============================================================
#define KA_AH 0
#define KA_BH (2*64*136*2)
#define KA_Q  (4*64*136*2)
#define KA_KV (KA_Q + 256*72*2)
#define KA_SMEM (KA_KV + 64*72*2)

__global__ __launch_bounds__(256, 1) void kvattn_kernel() {
    extern __shared__ char dynka[];
    uint32_t sb = smem_u32(dynka);
    uint32_t qbuf = sb + KA_Q, kvb = sb + KA_KV;
    int bh = blockIdx.x;
    int b = bh >> 3, hh = bh & 7;
    int tid = threadIdx.x, lane = tid & 31, wid = tid >> 5;

    int em = (wid & 3) * 16, dn = (wid >> 2) * 32;
    int nb = wid * 32;

    int a_row = lane & 15, a_col8 = (lane >> 4) * 8;
    int kb_row0 = dn + (lane & 7) + ((lane >> 4) << 3), kb_col = lane & 8;
    int ab_row0 = (lane & 7) + ((lane >> 4) << 3), ab_col = lane & 8;

    float vmn[2][8][4];
    #pragma unroll
    for (int i = 0; i < 2; i++)
        #pragma unroll
        for (int j = 0; j < 8; j++)
            #pragma unroll
            for (int p = 0; p < 4; p++) vmn[i][j][p] = 0.f;

    for (int t = 0; t < T_; t++) {
        int tb = t * B_ + b;
        const __half* vsrc = g_vh + ((size_t)tb * C_ + hh*64) * N_;
        const __half* ksrc = g_kh + ((size_t)tb * C_ + hh*64) * N_;

        #pragma unroll
        for (int r = 0; r < 8; r++) {
            int idx = tid + r * 256;
            int row = idx >> 3, chk = idx & 7;
            CP16(qbuf + (uint32_t)((row*72 + chk*8) * 2),
                 g_qT + ((size_t)tb * N_ + row) * C_ + hh*64 + chk*8);
        }
        #pragma unroll
        for (int r = 0; r < 2; r++) {
            int idx = tid + r * 256;
            int row = idx >> 3, chk = idx & 7;
            CP16(sb + KA_AH + (uint32_t)((row*136 + chk*8) * 2), vsrc + (size_t)row * N_ + chk*8);
            CP16(sb + KA_BH + (uint32_t)((row*136 + chk*8) * 2), ksrc + (size_t)row * N_ + chk*8);
        }
        CP_COMMIT();
        #pragma unroll
        for (int r = 0; r < 2; r++) {
            int idx = tid + r * 256;
            int row = idx >> 3, chk = idx & 7;
            CP16(sb + KA_AH + (uint32_t)(((64 + row)*136 + chk*8) * 2), vsrc + (size_t)row * N_ + 128 + chk*8);
            CP16(sb + KA_BH + (uint32_t)(((64 + row)*136 + chk*8) * 2), ksrc + (size_t)row * N_ + 128 + chk*8);
        }
        CP_COMMIT();

        float kacc[4][4];
        #pragma unroll
        for (int j = 0; j < 4; j++)
            #pragma unroll
            for (int p = 0; p < 4; p++) kacc[j][p] = 0.f;

        #pragma unroll
        for (int ch = 0; ch < 2; ch++) {
            if (ch == 0) CP_WAIT(1); else CP_WAIT(0);
            __syncthreads();
            uint32_t ahb = sb + KA_AH + ch * (64*136*2);
            uint32_t bhb = sb + KA_BH + ch * (64*136*2);
            #pragma unroll
            for (int ks = 0; ks < 8; ks++) {
                int kc = ks * 16;
                uint32_t bfr[4][2];
                #pragma unroll
                for (int jp = 0; jp < 2; jp++) {
                    uint32_t r4[4];
                    ldm_x4(r4, bhb + (uint32_t)(((kb_row0 + jp*16)*136 + kc + kb_col) * 2));
                    bfr[jp*2][0] = r4[0];   bfr[jp*2][1] = r4[1];
                    bfr[jp*2+1][0] = r4[2]; bfr[jp*2+1][1] = r4[3];
                }
                uint32_t a4[4];
                ldm_x4(a4, ahb + (uint32_t)(((em + a_row)*136 + kc + a_col8) * 2));
                #pragma unroll
                for (int j = 0; j < 4; j++)
                    mma16816(kacc[j], a4, bfr[j]);
            }
        }

        __syncthreads();
        #pragma unroll
        for (int j = 0; j < 4; j++) {
            int e0 = em + (lane >> 2);
            int d0 = dn + j*8 + 2*(lane & 3);
            *(uint32_t*)(dynka + KA_KV + ((e0)*72 + d0) * 2)     = hpair(kacc[j][0] * 0.125f, kacc[j][1] * 0.125f);
            *(uint32_t*)(dynka + KA_KV + ((e0 + 8)*72 + d0) * 2) = hpair(kacc[j][2] * 0.125f, kacc[j][3] * 0.125f);
        }
        __syncthreads();

        float acc[2][8][4];
        #pragma unroll
        for (int i = 0; i < 2; i++)
            #pragma unroll
            for (int j = 0; j < 8; j++)
                #pragma unroll
                for (int p = 0; p < 4; p++) acc[i][j][p] = 0.f;

        #pragma unroll
        for (int ks = 0; ks < 4; ks++) {
            int kc = ks * 16;
            uint32_t bfr[8][2];
            #pragma unroll
            for (int jp = 0; jp < 4; jp++) {
                uint32_t r4[4];
                ldm_x4(r4, kvb + (uint32_t)(((ab_row0 + jp*16)*72 + kc + ab_col) * 2));
                bfr[jp*2][0] = r4[0];   bfr[jp*2][1] = r4[1];
                bfr[jp*2+1][0] = r4[2]; bfr[jp*2+1][1] = r4[3];
            }
            #pragma unroll
            for (int i = 0; i < 2; i++) {
                uint32_t a4[4];
                ldm_x4(a4, qbuf + (uint32_t)(((nb + i*16 + a_row)*72 + kc + a_col8) * 2));
                #pragma unroll
                for (int j = 0; j < 8; j++)
                    mma16816(acc[i][j], a4, bfr[j]);
            }
        }

        #pragma unroll
        for (int i = 0; i < 2; i++) {
            #pragma unroll
            for (int j = 0; j < 8; j++) {
                int n0 = nb + i*16 + (lane >> 2);
                int e0 = j*8 + 2*(lane & 3);
                float s0 = lif_step(vmn[i][j][0], acc[i][j][0], 0.5f);
                float s1 = lif_step(vmn[i][j][1], acc[i][j][1], 0.5f);
                float s2 = lif_step(vmn[i][j][2], acc[i][j][2], 0.5f);
                float s3 = lif_step(vmn[i][j][3], acc[i][j][3], 0.5f);
                *(uint32_t*)(g_sT + ((size_t)tb * N_ + n0) * C_ + hh*64 + e0) = hpair(s0, s1);
                *(uint32_t*)(g_sT + ((size_t)tb * N_ + n0 + 8) * C_ + hh*64 + e0) = hpair(s2, s3);
            }
        }
        __syncthreads();
    }
}

// ============================================================
// K4: proj GEMM (M64) + bias + BN -> d_out.  grid = 2048.
// ============================================================
__global__ __launch_bounds__(256, 2) void proj_mma_kernel(
    const float* __restrict__ pbias, const float* __restrict__ pg, const float* __restrict__ pb,
    const float* __restrict__ pm, const float* __restrict__ pv, float* __restrict__ out)
{
    extern __shared__ char dynsmem[];
    uint32_t asb = smem_u32(dynsmem), bsb = asb + NSTG*A64_STAGE_BYTES;
    int tid = threadIdx.x, lane = tid & 31, wid = tid >> 5;
    int wm = (wid & 1) * 32, wn = (wid >> 1) * 32;
    int bx = blockIdx.x;
    int nt = bx & 1, mt = (bx >> 1) & 7, tb = bx >> 4;

    float scl[2][2], mean[2][2], beta[2][2], bias[2][2];
    #pragma unroll
    for (int i = 0; i < 2; i++)
        #pragma unroll
        for (int rh = 0; rh < 2; rh++) {
            int o = mt*64 + wm + i*16 + rh*8 + (lane >> 2);
            scl[i][rh]  = pg[o] / sqrtf(pv[o] + 1e-5f);
            mean[i][rh] = pm[o];
            beta[i][rh] = pb[o];
            bias[i][rh] = pbias[o];
        }

    float acc[2][4][4];
    #pragma unroll
    for (int i = 0; i < 2; i++)
        #pragma unroll
        for (int j = 0; j < 4; j++)
            #pragma unroll
            for (int p = 0; p < 4; p++) acc[i][j][p] = 0.f;

    int rowbase = tb * 256 + nt*128;
    gemm_pass64(asb, bsb, acc, 3, mt, g_sT, rowbase, tid, wm, wn, lane);

    #pragma unroll
    for (int i = 0; i < 2; i++) {
        #pragma unroll
        for (int j = 0; j < 4; j++) {
            #pragma unroll
            for (int rh = 0; rh < 2; rh++) {
                float y0 = ((acc[i][j][rh*2+0] + bias[i][rh]) - mean[i][rh]) * scl[i][rh] + beta[i][rh];
                float y1 = ((acc[i][j][rh*2+1] + bias[i][rh]) - mean[i][rh]) * scl[i][rh] + beta[i][rh];
                int o = mt*64 + wm + i*16 + rh*8 + (lane >> 2);
                int n = nt*128 + wn + j*8 + 2*(lane & 3);
                *(float2*)(out + ((size_t)tb * C_ + o) * N_ + n) = make_float2(y0, y1);
            }
        }
    }
}

// ============================================================
extern "C" void kernel_launch(void* const* d_in, const int* in_sizes, int n_in,
                              void* d_out, int out_size) {
    (void)in_sizes; (void)n_in; (void)out_size;
    const float* x  = (const float*)d_in[0];
    const float* qw = (const float*)d_in[1];
    const float* qg = (const float*)d_in[2];
    const float* qb = (const float*)d_in[3];
    const float* qm = (const float*)d_in[4];
    const float* qv = (const float*)d_in[5];
    const float* kw = (const float*)d_in[6];
    const float* kg = (const float*)d_in[7];
    const float* kb = (const float*)d_in[8];
    const float* km = (const float*)d_in[9];
    const float* kvv= (const float*)d_in[10];
    const float* vw = (const float*)d_in[11];
    const float* vg = (const float*)d_in[12];
    const float* vb = (const float*)d_in[13];
    const float* vm = (const float*)d_in[14];
    const float* vv = (const float*)d_in[15];
    const float* pw    = (const float*)d_in[16];
    const float* pbias = (const float*)d_in[17];
    const float* pg    = (const float*)d_in[18];
    const float* pb    = (const float*)d_in[19];
    const float* pm    = (const float*)d_in[20];
    const float* pv    = (const float*)d_in[21];

    cudaFuncSetAttribute(qkv_mma_kernel, cudaFuncAttributeMaxDynamicSharedMemorySize, GEMM64T4_SMEM);
    cudaFuncSetAttribute(proj_mma_kernel, cudaFuncAttributeMaxDynamicSharedMemorySize, GEMM64_SMEM);
    cudaFuncSetAttribute(kvattn_kernel, cudaFuncAttributeMaxDynamicSharedMemorySize, KA_SMEM);

    prep_kernel<<<2048, 256>>>(x, qw, kw, vw, pw);
    qkv_mma_kernel<<<dim3(512, 3), 256, GEMM64T4_SMEM>>>(qg, qb, qm, qv, kg, kb, km, kvv, vg, vb, vm, vv);
    kvattn_kernel<<<256, 256, KA_SMEM>>>();
    proj_mma_kernel<<<2048, 256, GEMM64_SMEM>>>(pbias, pg, pb, pm, pv, (float*)d_out);
}

// round 17
// speedup vs baseline: 1.1056x; 1.1056x over previous
#include <cuda_runtime.h>
#include <cuda_fp16.h>
#include <cstdint>

#define T_ 4
#define B_ 32
#define C_ 512
#define N_ 256
#define H_ 8
#define D_ 64
#define BCN_ (B_*C_*N_)
#define TBCN_ (T_*BCN_)

// ---- scratch ----
__device__ __half g_kh[TBCN_];         // [tb][c][n] fp16 spikes
__device__ __half g_vh[TBCN_];
__device__ __half g_qT[TBCN_];         // [tb][n][c] fp16 spikes
__device__ __half g_xsT[TBCN_];        // [t][b][n][c] spikes fp16 (K-major)
__device__ __half g_sT[TBCN_];         // [tb][n][c] attn spikes fp16
__device__ __half g_wl[4*2*C_*C_];     // [mat][limb][o][c] fp16 weight limbs

// ================= helpers =================
__device__ __forceinline__ uint32_t smem_u32(const void* p) {
    uint32_t a;
    asm("{ .reg .u64 t; cvta.to.shared.u64 t, %1; cvt.u32.u64 %0, t; }" : "=r"(a) : "l"(p));
    return a;
}

#define CP16(dst, src) \
    asm volatile("cp.async.cg.shared.global [%0], [%1], 16;" :: "r"(dst), "l"(src))
#define CP_COMMIT() asm volatile("cp.async.commit_group;" ::: "memory")
#define CP_WAIT(n)  asm volatile("cp.async.wait_group %0;" :: "n"(n) : "memory")

__device__ __forceinline__ void ldm_x4(uint32_t r[4], uint32_t addr) {
    asm volatile("ldmatrix.sync.aligned.m8n8.x4.shared.b16 {%0,%1,%2,%3}, [%4];"
        : "=r"(r[0]), "=r"(r[1]), "=r"(r[2]), "=r"(r[3]) : "r"(addr));
}
__device__ __forceinline__ void mma16816(float c[4], const uint32_t a[4], const uint32_t* b) {
    asm volatile("mma.sync.aligned.m16n8k16.row.col.f32.f16.f16.f32 "
        "{%0,%1,%2,%3}, {%4,%5,%6,%7}, {%8,%9}, {%0,%1,%2,%3};"
        : "+f"(c[0]), "+f"(c[1]), "+f"(c[2]), "+f"(c[3])
        : "r"(a[0]), "r"(a[1]), "r"(a[2]), "r"(a[3]), "r"(b[0]), "r"(b[1]));
}

__device__ __forceinline__ float lif_step(float& v, float x, float vth) {
    v += (x - v) * 0.5f;
    float s = (v >= vth) ? 1.0f : 0.0f;
    if (s != 0.0f) v = 0.0f;
    return s;
}
__device__ __forceinline__ uint32_t hpair(float lo, float hi) {
    return (uint32_t)__half_as_ushort(__float2half_rn(lo)) |
           ((uint32_t)__half_as_ushort(__float2half_rn(hi)) << 16);
}
__device__ __forceinline__ uint32_t hpack(__half lo, __half hi) {
    return (uint32_t)__half_as_ushort(lo) | ((uint32_t)__half_as_ushort(hi) << 16);
}

// ============================================================
// K0+K1 merged prep: blocks [0,1024) = weight limb split (x4 vec),
// blocks [1024,2048) = LIF(x) -> fp16 spikes [t][b][n][c].
// ============================================================
__global__ __launch_bounds__(256) void prep_kernel(
    const float* __restrict__ x,
    const float* __restrict__ qw, const float* __restrict__ kw,
    const float* __restrict__ vw, const float* __restrict__ pw)
{
    __shared__ __half Sb[64][72];
    if (blockIdx.x < 1024) {
        int i = blockIdx.x * 256 + threadIdx.x;      // 0..262143: float4 groups
        int mat = i >> 16, g = i & 65535;
        int idx = g * 4;
        const float* W = (mat == 0) ? qw : (mat == 1) ? kw : (mat == 2) ? vw : pw;
        float4 w4 = *(const float4*)(W + idx);
        float w[4] = {w4.x, w4.y, w4.z, w4.w};
        __half h1[4], h2[4];
        #pragma unroll
        for (int p = 0; p < 4; p++) {
            h1[p] = __float2half_rn(w[p]);
            float r1 = w[p] - __half2float(h1[p]);
            h2[p] = __float2half_rn(r1);
        }
        size_t base = (size_t)(mat * 2) * 262144 + idx;
        *(uint2*)(g_wl + base)          = make_uint2(hpack(h1[0], h1[1]), hpack(h1[2], h1[3]));
        *(uint2*)(g_wl + base + 262144) = make_uint2(hpack(h2[0], h2[1]), hpack(h2[2], h2[3]));
        return;
    }
    int bx = blockIdx.x - 1024;
    int ch = bx & 7, nt = (bx >> 3) & 3, b = bx >> 5;
    int tid = threadIdx.x;
    int c_l = tid >> 2, ng = tid & 3;
    int n_o = tid >> 2, u0 = tid & 3;
    float vm[16];
    #pragma unroll
    for (int j = 0; j < 16; j++) vm[j] = 0.f;

    for (int t = 0; t < T_; t++) {
        const float* xp = x + (((size_t)(t * B_ + b)) * C_ + ch * 64 + c_l) * N_ + nt * 64 + ng * 16;
        #pragma unroll
        for (int q = 0; q < 4; q++) {
            float4 xv = *(const float4*)(xp + q * 4);
            Sb[c_l][ng*16 + q*4 + 0] = __float2half_rn(lif_step(vm[q*4+0], xv.x, 1.0f));
            Sb[c_l][ng*16 + q*4 + 1] = __float2half_rn(lif_step(vm[q*4+1], xv.y, 1.0f));
            Sb[c_l][ng*16 + q*4 + 2] = __float2half_rn(lif_step(vm[q*4+2], xv.z, 1.0f));
            Sb[c_l][ng*16 + q*4 + 3] = __float2half_rn(lif_step(vm[q*4+3], xv.w, 1.0f));
        }
        __syncthreads();
        char* outb = (char*)(g_xsT + ((size_t)(t*B_ + b) * N_ + nt*64 + n_o) * C_ + ch*64);
        #pragma unroll
        for (int hf = 0; hf < 2; hf++) {
            int u = u0 + hf * 4;
            uint32_t rp[4];
            #pragma unroll
            for (int p = 0; p < 4; p++) {
                float lo = __half2float(Sb[u*8 + p*2][n_o]);
                float hi = __half2float(Sb[u*8 + p*2 + 1][n_o]);
                rp[p] = hpair(lo, hi);
            }
            *(uint4*)(outb + u*16) = make_uint4(rp[0], rp[1], rp[2], rp[3]);
        }
        __syncthreads();
    }
}

// ============================================================
// M64 GEMM machinery: 64x128 block, 8 warps (2m x 4n), warp 32x32.
// Single-t variant (proj) and t-paired variant (qkv).
// ============================================================
#define B_STAGE_BYTES (128*24*2)
#define B2_STAGE_BYTES (256*24*2)
#define A64_STAGE_BYTES (2*64*24*2)
#define NSTG 4
#define GEMM64_SMEM   (NSTG*A64_STAGE_BYTES + NSTG*B_STAGE_BYTES)
#define GEMM64T2_SMEM (NSTG*A64_STAGE_BYTES + NSTG*B2_STAGE_BYTES)

__device__ __forceinline__ void load_stage_B(uint32_t bsb, int s, int kc,
                                             const __half* srcT, int rowbase, int tid) {
    int n = tid >> 1, h = tid & 1;
    const __half* src = srcT + ((size_t)(rowbase + n)) * 512 + kc + h*8;
    uint32_t dst = bsb + (uint32_t)(((s*128 + n)*24 + h*8) * 2);
    CP16(dst, src);
}
__device__ __forceinline__ void load_stage_B2(uint32_t bsb, int s, int kc,
                                              const __half* srcT, int rb0, int rb1, int tid) {
    int n = tid >> 1, h = tid & 1;
    CP16(bsb + (uint32_t)(((s*256 + n)*24 + h*8) * 2),
         srcT + ((size_t)(rb0 + n)) * 512 + kc + h*8);
    CP16(bsb + (uint32_t)(((s*256 + 128 + n)*24 + h*8) * 2),
         srcT + ((size_t)(rb1 + n)) * 512 + kc + h*8);
}
__device__ __forceinline__ void load_stage_A64(uint32_t asb, int s, int kc, int wmat, int mt, int tid) {
    int l = tid >> 7, rem = tid & 127;
    int o = rem >> 1, h = rem & 1;
    const __half* src = g_wl + ((size_t)(wmat*2 + l) * 512 + mt*64 + o) * 512 + kc + h*8;
    uint32_t dst = asb + (uint32_t)((((s*2 + l)*64 + o)*24 + h*8) * 2);
    CP16(dst, src);
}

// single-t pass (proj)
__device__ __forceinline__ void gemm_pass64(uint32_t asb, uint32_t bsb, float acc[2][4][4],
                                            int wmat, int mt, const __half* srcT, int rowbase,
                                            int tid, int wm, int wn, int lane) {
    #pragma unroll
    for (int p = 0; p < 3; p++) {
        load_stage_A64(asb, p, p*16, wmat, mt, tid);
        load_stage_B(bsb, p, p*16, srcT, rowbase, tid);
        CP_COMMIT();
    }
    int a_row = lane & 15, a_col = (lane >> 4) * 8;
    int b_row = wn + (lane & 7) + ((lane >> 4) << 3), b_col = lane & 8;

    int s = 0;
    for (int c = 0; c < 32; c++) {
        CP_WAIT(2);
        __syncthreads();
        if (c + 3 < 32) {
            int ns = s + 3; if (ns >= NSTG) ns -= NSTG;
            load_stage_A64(asb, ns, (c+3)*16, wmat, mt, tid);
            load_stage_B(bsb, ns, (c+3)*16, srcT, rowbase, tid);
        }
        CP_COMMIT();

        uint32_t bfr[4][2];
        #pragma unroll
        for (int jp = 0; jp < 2; jp++) {
            uint32_t r4[4];
            ldm_x4(r4, bsb + (uint32_t)((((s*128) + b_row + jp*16)*24 + b_col) * 2));
            bfr[jp*2][0] = r4[0];   bfr[jp*2][1] = r4[1];
            bfr[jp*2+1][0] = r4[2]; bfr[jp*2+1][1] = r4[3];
        }
        #pragma unroll
        for (int l = 0; l < 2; l++) {
            #pragma unroll
            for (int i = 0; i < 2; i++) {
                uint32_t a4[4];
                ldm_x4(a4, asb + (uint32_t)(((((s*2 + l)*64) + wm + i*16 + a_row)*24 + a_col) * 2));
                #pragma unroll
                for (int j = 0; j < 4; j++)
                    mma16816(acc[i][j], a4, bfr[j]);
            }
        }
        if (++s >= NSTG) s = 0;
    }
}

// t-paired pass (qkv): acc[t][i][j][4], A frags reused for both t.
__device__ __forceinline__ void gemm_pass64_t2(uint32_t asb, uint32_t bsb, float acc[2][2][4][4],
                                               int wmat, int mt, const __half* srcT,
                                               int rb0, int rb1,
                                               int tid, int wm, int wn, int lane) {
    #pragma unroll
    for (int p = 0; p < 3; p++) {
        load_stage_A64(asb, p, p*16, wmat, mt, tid);
        load_stage_B2(bsb, p, p*16, srcT, rb0, rb1, tid);
        CP_COMMIT();
    }
    int a_row = lane & 15, a_col = (lane >> 4) * 8;
    int b_row = wn + (lane & 7) + ((lane >> 4) << 3), b_col = lane & 8;

    int s = 0;
    for (int c = 0; c < 32; c++) {
        CP_WAIT(2);
        __syncthreads();
        if (c + 3 < 32) {
            int ns = s + 3; if (ns >= NSTG) ns -= NSTG;
            load_stage_A64(asb, ns, (c+3)*16, wmat, mt, tid);
            load_stage_B2(bsb, ns, (c+3)*16, srcT, rb0, rb1, tid);
        }
        CP_COMMIT();

        uint32_t bfr[2][4][2];
        #pragma unroll
        for (int t = 0; t < 2; t++) {
            #pragma unroll
            for (int jp = 0; jp < 2; jp++) {
                uint32_t r4[4];
                ldm_x4(r4, bsb + (uint32_t)((((s*256 + t*128) + b_row + jp*16)*24 + b_col) * 2));
                bfr[t][jp*2][0] = r4[0];   bfr[t][jp*2][1] = r4[1];
                bfr[t][jp*2+1][0] = r4[2]; bfr[t][jp*2+1][1] = r4[3];
            }
        }
        #pragma unroll
        for (int l = 0; l < 2; l++) {
            #pragma unroll
            for (int i = 0; i < 2; i++) {
                uint32_t a4[4];
                ldm_x4(a4, asb + (uint32_t)(((((s*2 + l)*64) + wm + i*16 + a_row)*24 + a_col) * 2));
                #pragma unroll
                for (int t = 0; t < 2; t++)
                    #pragma unroll
                    for (int j = 0; j < 4; j++)
                        mma16816(acc[t][i][j], a4, bfr[t][j]);
            }
        }
        if (++s >= NSTG) s = 0;
    }
}

// ============================================================
// K2: qkv GEMM (M64, t-paired) + BN + LIF.  q writes g_qT [n][c],
// k/v write [c][n]; all branches stage tiles in smem for coalesced
// uint4 stores.  grid.x=512, grid.y=3.
// ============================================================
__global__ __launch_bounds__(256, 2) void qkv_mma_kernel(
    const float* __restrict__ qg, const float* __restrict__ qb, const float* __restrict__ qm, const float* __restrict__ qv,
    const float* __restrict__ kg, const float* __restrict__ kb, const float* __restrict__ km, const float* __restrict__ kvv,
    const float* __restrict__ vg, const float* __restrict__ vb, const float* __restrict__ vmn, const float* __restrict__ vvv)
{
    extern __shared__ char dynsmem[];
    uint32_t asb = smem_u32(dynsmem), bsb = asb + NSTG*A64_STAGE_BYTES;
    int tid = threadIdx.x, lane = tid & 31, wid = tid >> 5;
    int wm = (wid & 1) * 32, wn = (wid >> 1) * 32;
    int bx = blockIdx.x, br = blockIdx.y;
    int nt = bx & 1, mt = (bx >> 1) & 7, b = bx >> 4;

    const float* G  = (br == 0) ? qg : (br == 1) ? kg : vg;
    const float* Bt = (br == 0) ? qb : (br == 1) ? kb : vb;
    const float* M  = (br == 0) ? qm : (br == 1) ? km : vmn;
    const float* V  = (br == 0) ? qv : (br == 1) ? kvv : vvv;
    __half* outp = (br == 1) ? g_kh : g_vh;

    float scl[2][2], mean[2][2], beta[2][2];
    #pragma unroll
    for (int i = 0; i < 2; i++)
        #pragma unroll
        for (int rh = 0; rh < 2; rh++) {
            int o = mt*64 + wm + i*16 + rh*8 + (lane >> 2);
            scl[i][rh]  = G[o] / sqrtf(V[o] + 1e-5f);
            mean[i][rh] = M[o];
            beta[i][rh] = Bt[o];
        }

    float vm[2][2][4][2];
    #pragma unroll
    for (int i = 0; i < 2; i++)
        #pragma unroll
        for (int rh = 0; rh < 2; rh++)
            #pragma unroll
            for (int j = 0; j < 4; j++) { vm[i][rh][j][0] = 0.f; vm[i][rh][j][1] = 0.f; }

    for (int tp = 0; tp < 2; tp++) {
        float acc[2][2][4][4];
        #pragma unroll
        for (int t = 0; t < 2; t++)
            #pragma unroll
            for (int i = 0; i < 2; i++)
                #pragma unroll
                for (int j = 0; j < 4; j++)
                    #pragma unroll
                    for (int p = 0; p < 4; p++) acc[t][i][j][p] = 0.f;

        int t0 = tp*2, t1 = tp*2 + 1;
        int rb0 = (t0*B_ + b) * 256 + nt*128;
        int rb1 = (t1*B_ + b) * 256 + nt*128;
        gemm_pass64_t2(asb, bsb, acc, br, mt, g_xsT, rb0, rb1, tid, wm, wn, lane);

        #pragma unroll
        for (int t01 = 0; t01 < 2; t01++) {
            int t = tp*2 + t01;
            if (br == 0) {
                __syncthreads();
                __half* Sq = (__half*)dynsmem;   // [n 128][o 64] stride 72
                #pragma unroll
                for (int i = 0; i < 2; i++) {
                    #pragma unroll
                    for (int j = 0; j < 4; j++) {
                        #pragma unroll
                        for (int rh = 0; rh < 2; rh++) {
                            float y0 = (acc[t01][i][j][rh*2+0] - mean[i][rh]) * scl[i][rh] + beta[i][rh];
                            float y1 = (acc[t01][i][j][rh*2+1] - mean[i][rh]) * scl[i][rh] + beta[i][rh];
                            float s0 = lif_step(vm[i][rh][j][0], y0, 1.0f);
                            float s1 = lif_step(vm[i][rh][j][1], y1, 1.0f);
                            int o_l = wm + i*16 + rh*8 + (lane >> 2);
                            int n_l = wn + j*8 + 2*(lane & 3);
                            Sq[n_l*72 + o_l]     = __float2half_rn(s0);
                            Sq[(n_l+1)*72 + o_l] = __float2half_rn(s1);
                        }
                    }
                }
                __syncthreads();
                #pragma unroll
                for (int r = 0; r < 2; r++) {
                    int idx = tid + r * 256;
                    int row = idx >> 3, chk = idx & 7;
                    *(uint4*)(g_qT + ((size_t)(t*B_ + b) * N_ + nt*128 + row) * C_ + mt*64 + chk*8) =
                        *(const uint4*)(&Sq[row*72 + chk*8]);
                }
                __syncthreads();
            } else {
                __syncthreads();
                __half* Sk = (__half*)dynsmem;   // [o 64][n 128] stride 136
                #pragma unroll
                for (int i = 0; i < 2; i++) {
                    #pragma unroll
                    for (int j = 0; j < 4; j++) {
                        #pragma unroll
                        for (int rh = 0; rh < 2; rh++) {
                            float y0 = (acc[t01][i][j][rh*2+0] - mean[i][rh]) * scl[i][rh] + beta[i][rh];
                            float y1 = (acc[t01][i][j][rh*2+1] - mean[i][rh]) * scl[i][rh] + beta[i][rh];
                            float s0 = lif_step(vm[i][rh][j][0], y0, 1.0f);
                            float s1 = lif_step(vm[i][rh][j][1], y1, 1.0f);
                            int o_l = wm + i*16 + rh*8 + (lane >> 2);
                            int n_l = wn + j*8 + 2*(lane & 3);
                            *(uint32_t*)(&Sk[o_l*136 + n_l]) = hpair(s0, s1);
                        }
                    }
                }
                __syncthreads();
                #pragma unroll
                for (int r = 0; r < 4; r++) {
                    int idx = tid + r * 256;           // 1024 uint4: 64 rows x 16 chunks
                    int row = idx >> 4, chk = idx & 15;
                    *(uint4*)(outp + ((size_t)(t*B_ + b) * C_ + mt*64 + row) * N_ + nt*128 + chk*8) =
                        *(const uint4*)(&Sk[row*136 + chk*8]);
                }
                __syncthreads();
            }
        }
    }
}

// ============================================================
// K3 fused (verified round-13 version): per (b,h) block: for each
// t, kv = 0.125*v@k^T via MMA (kept in smem), then a = q@kv^T via
// MMA, LIF(0.5), spikes -> g_sT.
// ============================================================
#define KA_AH 0
#define KA_BH (2*64*136*2)
#define KA_Q  (4*64*136*2)
#define KA_KV (KA_Q + 256*72*2)
#define KA_SMEM (KA_KV + 64*72*2)

__global__ __launch_bounds__(256, 1) void kvattn_kernel() {
    extern __shared__ char dynka[];
    uint32_t sb = smem_u32(dynka);
    uint32_t qbuf = sb + KA_Q, kvb = sb + KA_KV;
    int bh = blockIdx.x;
    int b = bh >> 3, hh = bh & 7;
    int tid = threadIdx.x, lane = tid & 31, wid = tid >> 5;

    int em = (wid & 3) * 16, dn = (wid >> 2) * 32;
    int nb = wid * 32;

    int a_row = lane & 15, a_col8 = (lane >> 4) * 8;
    int kb_row0 = dn + (lane & 7) + ((lane >> 4) << 3), kb_col = lane & 8;
    int ab_row0 = (lane & 7) + ((lane >> 4) << 3), ab_col = lane & 8;

    float vmn[2][8][4];
    #pragma unroll
    for (int i = 0; i < 2; i++)
        #pragma unroll
        for (int j = 0; j < 8; j++)
            #pragma unroll
            for (int p = 0; p < 4; p++) vmn[i][j][p] = 0.f;

    for (int t = 0; t < T_; t++) {
        int tb = t * B_ + b;
        const __half* vsrc = g_vh + ((size_t)tb * C_ + hh*64) * N_;
        const __half* ksrc = g_kh + ((size_t)tb * C_ + hh*64) * N_;

        #pragma unroll
        for (int r = 0; r < 8; r++) {
            int idx = tid + r * 256;
            int row = idx >> 3, chk = idx & 7;
            CP16(qbuf + (uint32_t)((row*72 + chk*8) * 2),
                 g_qT + ((size_t)tb * N_ + row) * C_ + hh*64 + chk*8);
        }
        #pragma unroll
        for (int r = 0; r < 2; r++) {
            int idx = tid + r * 256;
            int row = idx >> 3, chk = idx & 7;
            CP16(sb + KA_AH + (uint32_t)((row*136 + chk*8) * 2), vsrc + (size_t)row * N_ + chk*8);
            CP16(sb + KA_BH + (uint32_t)((row*136 + chk*8) * 2), ksrc + (size_t)row * N_ + chk*8);
        }
        CP_COMMIT();
        #pragma unroll
        for (int r = 0; r < 2; r++) {
            int idx = tid + r * 256;
            int row = idx >> 3, chk = idx & 7;
            CP16(sb + KA_AH + (uint32_t)(((64 + row)*136 + chk*8) * 2), vsrc + (size_t)row * N_ + 128 + chk*8);
            CP16(sb + KA_BH + (uint32_t)(((64 + row)*136 + chk*8) * 2), ksrc + (size_t)row * N_ + 128 + chk*8);
        }
        CP_COMMIT();

        float kacc[4][4];
        #pragma unroll
        for (int j = 0; j < 4; j++)
            #pragma unroll
            for (int p = 0; p < 4; p++) kacc[j][p] = 0.f;

        #pragma unroll
        for (int ch = 0; ch < 2; ch++) {
            if (ch == 0) CP_WAIT(1); else CP_WAIT(0);
            __syncthreads();
            uint32_t ahb = sb + KA_AH + ch * (64*136*2);
            uint32_t bhb = sb + KA_BH + ch * (64*136*2);
            #pragma unroll
            for (int ks = 0; ks < 8; ks++) {
                int kc = ks * 16;
                uint32_t bfr[4][2];
                #pragma unroll
                for (int jp = 0; jp < 2; jp++) {
                    uint32_t r4[4];
                    ldm_x4(r4, bhb + (uint32_t)(((kb_row0 + jp*16)*136 + kc + kb_col) * 2));
                    bfr[jp*2][0] = r4[0];   bfr[jp*2][1] = r4[1];
                    bfr[jp*2+1][0] = r4[2]; bfr[jp*2+1][1] = r4[3];
                }
                uint32_t a4[4];
                ldm_x4(a4, ahb + (uint32_t)(((em + a_row)*136 + kc + a_col8) * 2));
                #pragma unroll
                for (int j = 0; j < 4; j++)
                    mma16816(kacc[j], a4, bfr[j]);
            }
        }

        __syncthreads();
        #pragma unroll
        for (int j = 0; j < 4; j++) {
            int e0 = em + (lane >> 2);
            int d0 = dn + j*8 + 2*(lane & 3);
            *(uint32_t*)(dynka + KA_KV + ((e0)*72 + d0) * 2)     = hpair(kacc[j][0] * 0.125f, kacc[j][1] * 0.125f);
            *(uint32_t*)(dynka + KA_KV + ((e0 + 8)*72 + d0) * 2) = hpair(kacc[j][2] * 0.125f, kacc[j][3] * 0.125f);
        }
        __syncthreads();

        float acc[2][8][4];
        #pragma unroll
        for (int i = 0; i < 2; i++)
            #pragma unroll
            for (int j = 0; j < 8; j++)
                #pragma unroll
                for (int p = 0; p < 4; p++) acc[i][j][p] = 0.f;

        #pragma unroll
        for (int ks = 0; ks < 4; ks++) {
            int kc = ks * 16;
            uint32_t bfr[8][2];
            #pragma unroll
            for (int jp = 0; jp < 4; jp++) {
                uint32_t r4[4];
                ldm_x4(r4, kvb + (uint32_t)(((ab_row0 + jp*16)*72 + kc + ab_col) * 2));
                bfr[jp*2][0] = r4[0];   bfr[jp*2][1] = r4[1];
                bfr[jp*2+1][0] = r4[2]; bfr[jp*2+1][1] = r4[3];
            }
            #pragma unroll
            for (int i = 0; i < 2; i++) {
                uint32_t a4[4];
                ldm_x4(a4, qbuf + (uint32_t)(((nb + i*16 + a_row)*72 + kc + a_col8) * 2));
                #pragma unroll
                for (int j = 0; j < 8; j++)
                    mma16816(acc[i][j], a4, bfr[j]);
            }
        }

        #pragma unroll
        for (int i = 0; i < 2; i++) {
            #pragma unroll
            for (int j = 0; j < 8; j++) {
                int n0 = nb + i*16 + (lane >> 2);
                int e0 = j*8 + 2*(lane & 3);
                float s0 = lif_step(vmn[i][j][0], acc[i][j][0], 0.5f);
                float s1 = lif_step(vmn[i][j][1], acc[i][j][1], 0.5f);
                float s2 = lif_step(vmn[i][j][2], acc[i][j][2], 0.5f);
                float s3 = lif_step(vmn[i][j][3], acc[i][j][3], 0.5f);
                *(uint32_t*)(g_sT + ((size_t)tb * N_ + n0) * C_ + hh*64 + e0) = hpair(s0, s1);
                *(uint32_t*)(g_sT + ((size_t)tb * N_ + n0 + 8) * C_ + hh*64 + e0) = hpair(s2, s3);
            }
        }
        __syncthreads();
    }
}

// ============================================================
// K4: proj GEMM (M64) + bias + BN -> d_out.  grid = 2048.
// ============================================================
__global__ __launch_bounds__(256, 2) void proj_mma_kernel(
    const float* __restrict__ pbias, const float* __restrict__ pg, const float* __restrict__ pb,
    const float* __restrict__ pm, const float* __restrict__ pv, float* __restrict__ out)
{
    extern __shared__ char dynsmem[];
    uint32_t asb = smem_u32(dynsmem), bsb = asb + NSTG*A64_STAGE_BYTES;
    int tid = threadIdx.x, lane = tid & 31, wid = tid >> 5;
    int wm = (wid & 1) * 32, wn = (wid >> 1) * 32;
    int bx = blockIdx.x;
    int nt = bx & 1, mt = (bx >> 1) & 7, tb = bx >> 4;

    float scl[2][2], mean[2][2], beta[2][2], bias[2][2];
    #pragma unroll
    for (int i = 0; i < 2; i++)
        #pragma unroll
        for (int rh = 0; rh < 2; rh++) {
            int o = mt*64 + wm + i*16 + rh*8 + (lane >> 2);
            scl[i][rh]  = pg[o] / sqrtf(pv[o] + 1e-5f);
            mean[i][rh] = pm[o];
            beta[i][rh] = pb[o];
            bias[i][rh] = pbias[o];
        }

    float acc[2][4][4];
    #pragma unroll
    for (int i = 0; i < 2; i++)
        #pragma unroll
        for (int j = 0; j < 4; j++)
            #pragma unroll
            for (int p = 0; p < 4; p++) acc[i][j][p] = 0.f;

    int rowbase = tb * 256 + nt*128;
    gemm_pass64(asb, bsb, acc, 3, mt, g_sT, rowbase, tid, wm, wn, lane);

    #pragma unroll
    for (int i = 0; i < 2; i++) {
        #pragma unroll
        for (int j = 0; j < 4; j++) {
            #pragma unroll
            for (int rh = 0; rh < 2; rh++) {
                float y0 = ((acc[i][j][rh*2+0] + bias[i][rh]) - mean[i][rh]) * scl[i][rh] + beta[i][rh];
                float y1 = ((acc[i][j][rh*2+1] + bias[i][rh]) - mean[i][rh]) * scl[i][rh] + beta[i][rh];
                int o = mt*64 + wm + i*16 + rh*8 + (lane >> 2);
                int n = nt*128 + wn + j*8 + 2*(lane & 3);
                *(float2*)(out + ((size_t)tb * C_ + o) * N_ + n) = make_float2(y0, y1);
            }
        }
    }
}

// ============================================================
extern "C" void kernel_launch(void* const* d_in, const int* in_sizes, int n_in,
                              void* d_out, int out_size) {
    (void)in_sizes; (void)n_in; (void)out_size;
    const float* x  = (const float*)d_in[0];
    const float* qw = (const float*)d_in[1];
    const float* qg = (const float*)d_in[2];
    const float* qb = (const float*)d_in[3];
    const float* qm = (const float*)d_in[4];
    const float* qv = (const float*)d_in[5];
    const float* kw = (const float*)d_in[6];
    const float* kg = (const float*)d_in[7];
    const float* kb = (const float*)d_in[8];
    const float* km = (const float*)d_in[9];
    const float* kvv= (const float*)d_in[10];
    const float* vw = (const float*)d_in[11];
    const float* vg = (const float*)d_in[12];
    const float* vb = (const float*)d_in[13];
    const float* vm = (const float*)d_in[14];
    const float* vv = (const float*)d_in[15];
    const float* pw    = (const float*)d_in[16];
    const float* pbias = (const float*)d_in[17];
    const float* pg    = (const float*)d_in[18];
    const float* pb    = (const float*)d_in[19];
    const float* pm    = (const float*)d_in[20];
    const float* pv    = (const float*)d_in[21];

    cudaFuncSetAttribute(qkv_mma_kernel, cudaFuncAttributeMaxDynamicSharedMemorySize, GEMM64T2_SMEM);
    cudaFuncSetAttribute(proj_mma_kernel, cudaFuncAttributeMaxDynamicSharedMemorySize, GEMM64_SMEM);
    cudaFuncSetAttribute(kvattn_kernel, cudaFuncAttributeMaxDynamicSharedMemorySize, KA_SMEM);

    prep_kernel<<<2048, 256>>>(x, qw, kw, vw, pw);
    qkv_mma_kernel<<<dim3(512, 3), 256, GEMM64T2_SMEM>>>(qg, qb, qm, qv, kg, kb, km, kvv, vg, vb, vm, vv);
    kvattn_kernel<<<256, 256, KA_SMEM>>>();
    proj_mma_kernel<<<2048, 256, GEMM64_SMEM>>>(pbias, pg, pb, pm, pv, (float*)d_out);
}